// round 11
// baseline (speedup 1.0000x reference)
#include <cuda_runtime.h>
#include <cuda_bf16.h>

#define BB 64
#define TT 512
#define DD 768
#define LL 50

typedef unsigned long long ull;

// ---------- f32x2 helpers (sm_103a packed fp32) ----------
__device__ __forceinline__ ull pack2(float x, float y) {
    ull r;
    asm("mov.b64 %0, {%1,%2};" : "=l"(r) : "f"(x), "f"(y));
    return r;
}
__device__ __forceinline__ void unpack2(ull v, float& x, float& y) {
    asm("mov.b64 {%0,%1}, %2;" : "=f"(x), "=f"(y) : "l"(v));
}
__device__ __forceinline__ void fma2(ull& d, ull a, ull b) {
    asm("fma.rn.f32x2 %0, %1, %2, %0;" : "+l"(d) : "l"(a), "l"(b));
}
__device__ __forceinline__ ull add2(ull a, ull b) {
    ull r;
    asm("add.rn.f32x2 %0, %1, %2;" : "=l"(r) : "l"(a), "l"(b));
    return r;
}
__device__ __forceinline__ float frcp_fast(float x) {
    float r;
    asm("rcp.approx.f32 %0, %1;" : "=f"(r) : "f"(x));
    return r;
}
__device__ __forceinline__ float wred_addf(float x) {
#pragma unroll
    for (int o = 16; o > 0; o >>= 1) x += __shfl_xor_sync(0xffffffffu, x, o);
    return x;
}
__device__ __forceinline__ int wred_addi(int x) {
#pragma unroll
    for (int o = 16; o > 0; o >>= 1) x += __shfl_xor_sync(0xffffffffu, x, o);
    return x;
}

// ---------- GEMM: logits = emb @ W + b  (register double-buffered) ----------
#define AP 129
__global__ void __launch_bounds__(128, 2)
gemm_kernel(const float* __restrict__ A, const float* __restrict__ W,
            const float* __restrict__ bias, float* __restrict__ logits,
            float* __restrict__ loss0) {
    __shared__ float Ash[64 * AP];               // [kk][row] transposed
    __shared__ __align__(16) float Wsh[64 * 52]; // [kk][j] pad 52
    __shared__ float bsh[52];

    int tid = threadIdx.x;
    if (blockIdx.x == 0 && tid == 0) *loss0 = 0.0f;
    if (tid < 52) bsh[tid] = (tid < LL) ? bias[tid] : 0.0f;

    ull acc[26];
#pragma unroll
    for (int p = 0; p < 26; p++) acc[p] = 0ull;

    const float4* Ag = reinterpret_cast<const float4*>(A);
    int rowbase = blockIdx.x * 128;

    float4 fa[16];
    float wv[26];

    // prefetch tile 0
#pragma unroll
    for (int it = 0; it < 16; it++) {
        int idx = it * 128 + tid;
        int q = idx & 15;
        int r = idx >> 4;
        fa[it] = Ag[(size_t)(rowbase + r) * (DD / 4) + q];
    }
#pragma unroll
    for (int it = 0; it < 26; it++) {
        int idx = it * 128 + tid;
        int kk = idx / 52;
        int j = idx - kk * 52;
        wv[it] = (j < LL) ? W[(size_t)kk * LL + j] : 0.0f;
    }

    for (int kt = 0; kt < DD / 64; kt++) {
        __syncthreads();
#pragma unroll
        for (int it = 0; it < 16; it++) {
            int idx = it * 128 + tid;
            int q = idx & 15;
            int r = idx >> 4;
            Ash[(4 * q + 0) * AP + r] = fa[it].x;
            Ash[(4 * q + 1) * AP + r] = fa[it].y;
            Ash[(4 * q + 2) * AP + r] = fa[it].z;
            Ash[(4 * q + 3) * AP + r] = fa[it].w;
        }
#pragma unroll
        for (int it = 0; it < 26; it++) {
            int idx = it * 128 + tid;
            if (idx < 64 * 52) Wsh[idx] = wv[it];
        }
        if (kt < DD / 64 - 1) {
#pragma unroll
            for (int it = 0; it < 16; it++) {
                int idx = it * 128 + tid;
                int q = idx & 15;
                int r = idx >> 4;
                fa[it] = Ag[(size_t)(rowbase + r) * (DD / 4) + (kt + 1) * 16 + q];
            }
#pragma unroll
            for (int it = 0; it < 26; it++) {
                int idx = it * 128 + tid;
                int kk = idx / 52;
                int j = idx - kk * 52;
                wv[it] = (j < LL) ? W[(size_t)((kt + 1) * 64 + kk) * LL + j] : 0.0f;
            }
        }
        __syncthreads();
#pragma unroll 8
        for (int kk = 0; kk < 64; kk++) {
            float a = Ash[kk * AP + tid];
            ull ap = pack2(a, a);
            const ulonglong2* w2 = reinterpret_cast<const ulonglong2*>(Wsh + kk * 52);
#pragma unroll
            for (int p = 0; p < 13; p++) {
                ulonglong2 w = w2[p];
                fma2(acc[2 * p + 0], ap, w.x);
                fma2(acc[2 * p + 1], ap, w.y);
            }
        }
    }
    __syncthreads();
    float* st = Ash;
#pragma unroll
    for (int p = 0; p < 25; p++) {
        float x, y;
        unpack2(acc[p], x, y);
        st[tid * 50 + 2 * p + 0] = x + bsh[2 * p + 0];
        st[tid * 50 + 2 * p + 1] = y + bsh[2 * p + 1];
    }
    __syncthreads();
    size_t base = (size_t)blockIdx.x * (128 * LL);
    for (int idx = tid; idx < 128 * LL; idx += 128)
        logits[base + idx] = st[idx];
}

// ---------- mask decode ----------
__device__ __forceinline__ bool mask_on(const void* m, int mode, int idx) {
    if (mode == 0) return ((const int*)m)[idx] != 0;
    if (mode == 1) return ((const unsigned char*)m)[idx] != 0;
    return ((const float*)m)[idx] != 0.0f;
}

// ---------- CRF: one block per batch, fwd+bwd split, NO big smem ----------
// Emissions streamed from gmem via depth-4 register rings (unroll 4 keeps
// ring indices constant -> loads run 4 steps ahead, no rotation MOVs).
__global__ void __launch_bounds__(128, 1)
crf_kernel(const float* __restrict__ logits, const int* __restrict__ labels,
           const void* __restrict__ maskraw, const float* __restrict__ startT,
           const float* __restrict__ endT, const float* __restrict__ trans,
           float* __restrict__ loss0) {
    __shared__ __align__(16) ull pdf[2][32], pdb[2][32];
    __shared__ float vf[64], vb[64];
    __shared__ float Ssh[2];
    __shared__ float res_den, res_num;

    int b = blockIdx.x;
    int tid = threadIdx.x;
    int wid = tid >> 5;
    int u = tid & 31;

    const float* lrow0 = logits + (size_t)b * TT * LL;

    int mw = *(const int*)maskraw;
    int mode = (mw == 1) ? 0 : ((mw == 0x01010101) ? 1 : 2);
    int cnt = 0;
    for (int t = u; t < TT; t += 32) cnt += mask_on(maskraw, mode, b * TT + t) ? 1 : 0;
    int len = wred_addi(cnt);
    int m = len >> 1;

    if (tid < 64) { vf[tid] = 0.0f; vb[tid] = 0.0f; }
    __syncthreads();

    int j0 = 2 * u, j1 = 2 * u + 1;
    bool act = (u < 25);
    int jc = act ? j0 : 0;

    if (wid == 0) {
        // ---- forward: alpha over [0..m] ----
        ull EF0[25], EF1[25];
#pragma unroll
        for (int i = 0; i < 25; i++) {
            float a0 = 0.0f, a1 = 0.0f, d0 = 0.0f, d1 = 0.0f;
            if (act) {
                a0 = __expf(trans[(2 * i) * LL + j0]);
                a1 = __expf(trans[(2 * i + 1) * LL + j0]);
                d0 = __expf(trans[(2 * i) * LL + j1]);
                d1 = __expf(trans[(2 * i + 1) * LL + j1]);
            }
            EF0[i] = pack2(a0, a1);
            EF1[i] = pack2(d0, d1);
        }

        float vx = 0.0f, vy = 0.0f;
        if (act) {
            vx = __expf(startT[j0] + lrow0[j0]);
            vy = __expf(startT[j1] + lrow0[j1]);
        }
        float S = 0.0f;

        // depth-4 emission ring: slot(t) = (t-1)&3 holds logit row t
        float lgx[4], lgy[4];
#pragma unroll
        for (int k = 0; k < 4; k++) {
            size_t o = (size_t)(1 + k) * LL + jc;
            lgx[k] = lrow0[o];
            lgy[k] = lrow0[o + 1];
        }

#pragma unroll 4
        for (int t = 1; t <= m; t++) {
            int slot = (t - 1) & 3;
            int buf = t & 1;
            pdf[buf][u] = pack2(vx, vy);
            __syncwarp();
            float wx = __expf(lgx[slot]);
            float wy = __expf(lgy[slot]);
            const ulonglong2* pp2 = reinterpret_cast<const ulonglong2*>(pdf[buf]);
            ull A0 = 0ull, A1 = 0ull, A2 = 0ull, A3 = 0ull;
            ull B0 = 0ull, B1 = 0ull, B2 = 0ull, B3 = 0ull;
            ulonglong2 Pq0 = pp2[0];
            float v0b, dmy;
            unpack2(Pq0.x, v0b, dmy);
            fma2(A0, Pq0.x, EF0[0]);
            fma2(A1, Pq0.y, EF0[1]);
            fma2(B0, Pq0.x, EF1[0]);
            fma2(B1, Pq0.y, EF1[1]);
#pragma unroll
            for (int q = 1; q < 12; q++) {
                ulonglong2 Pq = pp2[q];
                if (q & 1) {
                    fma2(A2, Pq.x, EF0[2 * q]);
                    fma2(A3, Pq.y, EF0[2 * q + 1]);
                    fma2(B2, Pq.x, EF1[2 * q]);
                    fma2(B3, Pq.y, EF1[2 * q + 1]);
                } else {
                    fma2(A0, Pq.x, EF0[2 * q]);
                    fma2(A1, Pq.y, EF0[2 * q + 1]);
                    fma2(B0, Pq.x, EF1[2 * q]);
                    fma2(B1, Pq.y, EF1[2 * q + 1]);
                }
            }
            ull P24 = pdf[buf][24];
            fma2(A2, P24, EF0[24]);
            fma2(B2, P24, EF1[24]);
            float r = frcp_fast(v0b);
            S += __logf(v0b);
            ull sA = add2(add2(A0, A1), add2(A2, A3));
            ull sB = add2(add2(B0, B1), add2(B2, B3));
            float e0, e1, f0, f1;
            unpack2(sA, e0, e1);
            unpack2(sB, f0, f1);
            vx = (e0 + e1) * wx * r;
            vy = (f0 + f1) * wy * r;
            int tp = t + 4;
            if (tp > TT - 1) tp = TT - 1;
            size_t o = (size_t)tp * LL + jc;
            lgx[slot] = lrow0[o];
            lgy[slot] = lrow0[o + 1];
        }

        if (act) { vf[j0] = vx; vf[j1] = vy; }
        if (u == 0) Ssh[0] = S;
    } else if (wid == 1) {
        // ---- backward: beta over [len-1..m] ----
        ull EB0[25], EB1[25];
#pragma unroll
        for (int k = 0; k < 25; k++) {
            float a0 = 0.0f, a1 = 0.0f, d0 = 0.0f, d1 = 0.0f;
            if (act) {
                a0 = __expf(trans[j0 * LL + 2 * k]);
                a1 = __expf(trans[j0 * LL + 2 * k + 1]);
                d0 = __expf(trans[j1 * LL + 2 * k]);
                d1 = __expf(trans[j1 * LL + 2 * k + 1]);
            }
            EB0[k] = pack2(a0, a1);
            EB1[k] = pack2(d0, d1);
        }

        float ux = 0.0f, uy = 0.0f;
        if (act) {
            ux = __expf(endT[j0]);
            uy = __expf(endT[j1]);
        }
        float S = 0.0f;

        // depth-4 ring: iteration s uses logit row (len-1-s); slot = s&3
        float lgx[4], lgy[4];
#pragma unroll
        for (int k = 0; k < 4; k++) {
            int tt = len - 1 - k;
            if (tt < 0) tt = 0;
            size_t o = (size_t)tt * LL + jc;
            lgx[k] = lrow0[o];
            lgy[k] = lrow0[o + 1];
        }

        int smax = len - 2 - m;  // s = 0..smax, cur = len-2-s
#pragma unroll 4
        for (int s = 0; s <= smax; s++) {
            int slot = s & 3;
            int buf = s & 1;
            float wx = __expf(lgx[slot]);
            float wy = __expf(lgy[slot]);
            pdb[buf][u] = pack2(ux * wx, uy * wy);  // q = w_{cur+1} ∘ u
            __syncwarp();
            const ulonglong2* pp2 = reinterpret_cast<const ulonglong2*>(pdb[buf]);
            ull A0 = 0ull, A1 = 0ull, A2 = 0ull, A3 = 0ull;
            ull B0 = 0ull, B1 = 0ull, B2 = 0ull, B3 = 0ull;
            ulonglong2 Pq0 = pp2[0];
            float q0b, dmy;
            unpack2(Pq0.x, q0b, dmy);
            fma2(A0, Pq0.x, EB0[0]);
            fma2(A1, Pq0.y, EB0[1]);
            fma2(B0, Pq0.x, EB1[0]);
            fma2(B1, Pq0.y, EB1[1]);
#pragma unroll
            for (int q = 1; q < 12; q++) {
                ulonglong2 Pq = pp2[q];
                if (q & 1) {
                    fma2(A2, Pq.x, EB0[2 * q]);
                    fma2(A3, Pq.y, EB0[2 * q + 1]);
                    fma2(B2, Pq.x, EB1[2 * q]);
                    fma2(B3, Pq.y, EB1[2 * q + 1]);
                } else {
                    fma2(A0, Pq.x, EB0[2 * q]);
                    fma2(A1, Pq.y, EB0[2 * q + 1]);
                    fma2(B0, Pq.x, EB1[2 * q]);
                    fma2(B1, Pq.y, EB1[2 * q + 1]);
                }
            }
            ull P24 = pdb[buf][24];
            fma2(A2, P24, EB0[24]);
            fma2(B2, P24, EB1[24]);
            float r = frcp_fast(q0b);
            S += __logf(q0b);
            ull sA = add2(add2(A0, A1), add2(A2, A3));
            ull sB = add2(add2(B0, B1), add2(B2, B3));
            float e0, e1, f0, f1;
            unpack2(sA, e0, e1);
            unpack2(sB, f0, f1);
            ux = (e0 + e1) * r;
            uy = (f0 + f1) * r;
            int tp = len - 1 - (s + 4);
            if (tp < 0) tp = 0;
            size_t o = (size_t)tp * LL + jc;
            lgx[slot] = lrow0[o];
            lgy[slot] = lrow0[o + 1];
        }

        if (act) { vb[j0] = ux; vb[j1] = uy; }
        if (u == 0) Ssh[1] = S;
    } else if (wid == 2) {
        // ---- numerator (prefix mask => prev tag = labels[t-1]) ----
        float np = 0.0f;
        const int* lab = labels + b * TT;
        for (int t = u; t < len; t += 32) {
            int tag = lab[t];
            float emv = lrow0[(size_t)t * LL + tag];
            np += (t == 0) ? (startT[tag] + emv)
                           : (trans[lab[t - 1] * LL + tag] + emv);
            if (t == len - 1) np += endT[tag];
        }
        float num = wred_addf(np);
        if (u == 0) res_num = num;
    }
    __syncthreads();

    // combine: den = log(dot(vf,vb)) + Sf + Sb
    if (wid == 0) {
        float s = act ? (vf[j0] * vb[j0] + vf[j1] * vb[j1]) : 0.0f;
        s = wred_addf(s);
        if (u == 0) res_den = __logf(s) + Ssh[0] + Ssh[1];
    }
    __syncthreads();
    if (tid == 0) atomicAdd(loss0, (res_den - res_num) * (1.0f / (float)BB));
}

extern "C" void kernel_launch(void* const* d_in, const int* in_sizes, int n_in,
                              void* d_out, int out_size) {
    (void)in_sizes; (void)n_in; (void)out_size;
    const float* emb    = (const float*)d_in[0];
    const int*   labels = (const int*)d_in[1];
    const void*  mask   = d_in[2];
    const float* W      = (const float*)d_in[3];
    const float* bias   = (const float*)d_in[4];
    const float* startT = (const float*)d_in[5];
    const float* endT   = (const float*)d_in[6];
    const float* trans  = (const float*)d_in[7];

    float* out = (float*)d_out;
    float* logits = out + 1;  // output layout: [ -loss, logits(B*T*L) ]

    gemm_kernel<<<256, 128>>>(emb, W, bias, logits, out);
    crf_kernel<<<BB, 128>>>(logits, labels, mask, startT, endT, trans, out);
}